// round 16
// baseline (speedup 1.0000x reference)
#include <cuda_runtime.h>
#include <cuda_fp16.h>
#include <cstdint>

// ---------------- problem constants ----------------
constexpr int S_TOK = 4096;
constexpr int DDIM  = 1024;
constexpr int HDIM  = 2816;
constexpr int NEXP  = 8;
constexpr int TOPK  = 2;

constexpr int BM = 128, BN = 128, BKH = 32;   // tile sizes (BKH in halves)
constexpr int MAXROWS = 9216;
constexpr int PERSIST = 304;                  // 2 CTAs/SM x 152 SMs
constexpr int CVT2 = 256;                     // w2 convert slabs
constexpr int NSTG = 5;                       // cp.async pipeline stages

// ---------------- device scratch (allocation-free) ----------------
__device__ __align__(16) __half g_xh[(long long)S_TOK * DDIM];
__device__ __align__(16) __half g_w1h[(long long)NEXP * DDIM * HDIM];  // [E][D][H]
__device__ __align__(16) __half g_w2h[(long long)NEXP * HDIM * DDIM];  // [E][H][D]
__device__ __align__(16) __half g_h[(long long)MAXROWS * HDIM];       // silu(x@w1+b1)
__device__ int    g_perm[MAXROWS];            // row -> token (-1 = pad)
__device__ float  g_rw[MAXROWS];              // row -> gate weight
__device__ int    g_off[NEXP + 1];
__device__ int    g_cnt[NEXP];
__device__ int    g_cur[NEXP];
__device__ int    g_tick[2];                  // persistent tile tickets
__device__ int    g_tok_e[TOPK * S_TOK];
__device__ float  g_tok_w[TOPK * S_TOK];

// ---------------- PTX helpers ----------------
// .cg: bypass L1 allocation (operands are streamed once; don't pollute L1)
#define CP16(d, s, b) \
    asm volatile("cp.async.cg.shared.global [%0], [%1], 16, %2;\n" :: "r"(d), "l"(s), "r"(b))
#define CPCOMMIT() asm volatile("cp.async.commit_group;\n" ::: "memory")
#define CPWAIT3()  asm volatile("cp.async.wait_group 3;\n" ::: "memory")
#define CPWAIT2()  asm volatile("cp.async.wait_group 2;\n" ::: "memory")
#define CPWAIT1()  asm volatile("cp.async.wait_group 1;\n" ::: "memory")
#define CPWAIT0()  asm volatile("cp.async.wait_group 0;\n" ::: "memory")

#define LDSM4(r0, r1, r2, r3, a) \
    asm volatile("ldmatrix.sync.aligned.m8n8.x4.shared.b16 {%0,%1,%2,%3}, [%4];" \
                 : "=r"(r0), "=r"(r1), "=r"(r2), "=r"(r3) : "r"(a))
#define LDSM4T(r0, r1, r2, r3, a) \
    asm volatile("ldmatrix.sync.aligned.m8n8.x4.trans.shared.b16 {%0,%1,%2,%3}, [%4];" \
                 : "=r"(r0), "=r"(r1), "=r"(r2), "=r"(r3) : "r"(a))

#define MMA16816(c, a, b) \
    asm volatile("mma.sync.aligned.m16n8k16.row.col.f32.f16.f16.f32 " \
                 "{%0,%1,%2,%3},{%4,%5,%6,%7},{%8,%9},{%0,%1,%2,%3};" \
                 : "+f"((c)[0]), "+f"((c)[1]), "+f"((c)[2]), "+f"((c)[3]) \
                 : "r"((a)[0]), "r"((a)[1]), "r"((a)[2]), "r"((a)[3]), \
                   "r"((b)[0]), "r"((b)[1]))

// smem swizzles (16B chunk granularity)
__device__ __forceinline__ uint32_t swzA(int r, int c) {   // A: 128 rows x 4 chunks
    return (uint32_t)((r * 4 + (c ^ ((r >> 1) & 3))) << 4);
}
__device__ __forceinline__ uint32_t swzB(int k, int c) {   // B: 32 rows x 16 chunks
    return (uint32_t)((k * 16 + (c ^ (k & 7))) << 4);
}

// ---------------- small kernels ----------------
__global__ void init_kernel() {
    int t = threadIdx.x;
    if (t < NEXP) { g_cnt[t] = 0; g_cur[t] = 0; }
    if (t < 2) g_tick[t] = 0;
}

// Fused setup: [0,512) gate (+x->fp16), [512,1024) zero out, [1024,2048) convert w1.
__global__ void __launch_bounds__(256)
setup_kernel(const float* __restrict__ x, const float* __restrict__ wg,
             const float* __restrict__ bg, const float* __restrict__ w1,
             float* __restrict__ out) {
    __shared__ float swg[NEXP][DDIM];          // w_gate transposed, 32 KB
    const int bid = blockIdx.x, tid = threadIdx.x;
    if (bid < 512) {
        // ---- stage w_gate into smem transposed (coalesced gmem reads) ----
        for (int t = tid; t < DDIM * NEXP; t += 256) {
            float v = wg[t];
            swg[t & (NEXP - 1)][t >> 3] = v;
        }
        __syncthreads();
        // ---- gate: one warp per token ----
        int warp = bid * 8 + (tid >> 5);
        int lane = tid & 31;
        const float* xr = x + (long long)warp * DDIM;
        float xv[32];
#pragma unroll
        for (int i = 0; i < 32; i++) xv[i] = xr[lane + 32 * i];
        __half* xh = g_xh + (long long)warp * DDIM;
#pragma unroll
        for (int i = 0; i < 32; i++) xh[lane + 32 * i] = __float2half_rn(xv[i]);

        float lg[NEXP];
#pragma unroll
        for (int e = 0; e < NEXP; e++) {
            float s = 0.f;
#pragma unroll
            for (int i = 0; i < 32; i++) s += xv[i] * swg[e][lane + 32 * i];
#pragma unroll
            for (int o = 16; o > 0; o >>= 1) s += __shfl_xor_sync(0xffffffffu, s, o);
            lg[e] = s + bg[e];
        }
        if (lane == 0) {
            int e0 = 0;
#pragma unroll
            for (int e = 1; e < NEXP; e++) if (lg[e] > lg[e0]) e0 = e;
            int e1 = -1;
#pragma unroll
            for (int e = 0; e < NEXP; e++) {
                if (e == e0) continue;
                if (e1 < 0 || lg[e] > lg[e1]) e1 = e;
            }
            float z  = expf(lg[e1] - lg[e0]);
            float w0 = 1.f / (1.f + z);
            float w1v = z / (1.f + z);
            g_tok_e[warp] = e0; g_tok_e[S_TOK + warp] = e1;
            g_tok_w[warp] = w0; g_tok_w[S_TOK + warp] = w1v;
            atomicAdd(&g_cnt[e0], 1);
            atomicAdd(&g_cnt[e1], 1);
        }
    } else if (bid < 1024) {
        // ---- zero the output (poisoned by harness) ----
        float4 z; z.x = z.y = z.z = z.w = 0.f;
        float4* o4 = reinterpret_cast<float4*>(out);
        int base = (bid - 512) * 2048 + tid;
#pragma unroll
        for (int j = 0; j < 8; j++) o4[base + j * 256] = z;
    } else {
        // ---- convert w1 -> fp16 ----
        int slab = bid - 1024;                      // 1024 slabs * 5632 chunks
        const float4* s4 = reinterpret_cast<const float4*>(w1);
        long long base = (long long)slab * 5632 + tid;
#pragma unroll
        for (int j = 0; j < 22; j++) {
            long long i = base + j * 256;
            float4 v = s4[i];
            __half2* d = reinterpret_cast<__half2*>(g_w1h) + i * 2;
            d[0] = __floats2half2_rn(v.x, v.y);
            d[1] = __floats2half2_rn(v.z, v.w);
        }
    }
}

__global__ void offsets_kernel() {
    if (threadIdx.x == 0) {
        int o = 0;
        for (int e = 0; e < NEXP; e++) {
            g_off[e] = o;
            o += ((g_cnt[e] + BM - 1) / BM) * BM;
        }
        g_off[NEXP] = o;
    }
    for (int i = threadIdx.x; i < MAXROWS; i += blockDim.x) g_perm[i] = -1;
}

// warp-aggregated scatter: one atomic per (warp, expert-group) instead of per thread
__global__ void scatter_kernel() {
    int t = blockIdx.x * blockDim.x + threadIdx.x;
    int lane = threadIdx.x & 31;
    if (t >= S_TOK) return;
#pragma unroll
    for (int k = 0; k < TOPK; k++) {
        int e = g_tok_e[k * S_TOK + t];
        unsigned grp = __match_any_sync(0xffffffffu, e);
        int leader = __ffs(grp) - 1;
        int rank = __popc(grp & ((1u << lane) - 1u));
        int base = 0;
        if (lane == leader) base = atomicAdd(&g_cur[e], __popc(grp));
        base = __shfl_sync(0xffffffffu, base, leader);
        int p = g_off[e] + base + rank;
        g_perm[p] = t;
        g_rw[p]   = g_tok_w[k * S_TOK + t];
    }
}

// w2 fp32->fp16 convert, one slab (runs as cheap tail tickets of GEMM1)
__device__ __forceinline__ void cvt_w2_slab(const float* __restrict__ w2,
                                            int slab, int tid) {
    const float4* s4 = reinterpret_cast<const float4*>(w2);
    long long base = (long long)slab * 22528 + tid;   // 256 slabs * 22528 chunks
#pragma unroll 4
    for (int j = 0; j < 88; j++) {
        long long i = base + (long long)j * 256;
        float4 v = s4[i];
        __half2* d = reinterpret_cast<__half2*>(g_w2h) + i * 2;
        d[0] = __floats2half2_rn(v.x, v.y);
        d[1] = __floats2half2_rn(v.z, v.w);
    }
}

// ---------------- persistent fp16 grouped GEMM (5-stage pipeline) ----------------
// FIRST : g_h = silu(gather(g_xh) @ g_w1h[e] + b1[e])     (K=1024, N=2816)
//         + w2 fp16 conversion tickets appended at the END of the stream
// !FIRST: out[token] += g_rw[row] * (g_h[row] @ g_w2h[e] + b2[e])  (K=2816, N=1024)
template <bool FIRST>
__global__ void __launch_bounds__(256, 2)
moe_gemm_h(const float* __restrict__ bias, float* __restrict__ out,
           const float* __restrict__ w2raw) {
    constexpr int KD = FIRST ? DDIM : HDIM;
    constexpr int ND = FIRST ? HDIM : DDIM;
    constexpr int KT = KD / BKH;
    constexpr int NT = ND / BN;
    constexpr uint32_t ASTG = BM * BKH * 2;   // 8 KB
    constexpr uint32_t BSTG = BKH * BN * 2;   // 8 KB

    __shared__ __align__(16) __half sA[NSTG][BM * BKH];   // 40 KB
    __shared__ __align__(16) __half sB[NSTG][BKH * BN];   // 40 KB
    __shared__ int s_tile;

    const int tid = threadIdx.x, lane = tid & 31, wid = tid >> 5;
    const uint32_t aB = (uint32_t)__cvta_generic_to_shared(&sA[0][0]);
    const uint32_t bB = (uint32_t)__cvta_generic_to_shared(&sB[0][0]);

    const int MT = g_off[NEXP] >> 7;     // active M tiles
    const int ntiles = MT * NT;
    const int total = ntiles + (FIRST ? CVT2 : 0);

    // warp layout: 2 (m) x 4 (n); warp tile 64 x 32
    const int wm = wid & 1, wn = wid >> 1;
    const int tl = lane >> 3, lr = lane & 7;
    const int arb = wm * 64 + (tl & 1) * 8 + lr;   // A ldmatrix row base
    const int acb = tl >> 1;                       // A chunk add (k8 block)
    const int bkb = (tl & 1) * 8 + lr;             // B k base within k16
    const int bcb = wn * 4 + (tl >> 1);            // B chunk base

    for (;;) {
        __syncthreads();
        if (tid == 0) s_tile = atomicAdd(&g_tick[FIRST ? 0 : 1], 1);
        __syncthreads();
        const int t = s_tile;
        if (t >= total) break;

        if (FIRST && t >= ntiles) {          // cheap cvt tickets pack the last wave
            cvt_w2_slab(w2raw, t - ntiles, tid);
            continue;
        }
        const int m0 = (t % MT) * BM;        // m-fastest: concurrent CTAs share B tiles
        const int n0 = (t / MT) * BN;

        int e = 0;
#pragma unroll
        for (int i = 1; i < NEXP; i++) if (m0 >= g_off[i]) e = i;

        const __half* Ag = FIRST ? g_xh : g_h;
        const __half* Bg = (FIRST ? g_w1h : g_w2h) + (long long)e * KD * ND;

        // ---- per-thread cp.async plans (2 x 16B chunks each for A and B) ----
        const __half* asrc[2]; uint32_t adst[2], abyt[2];
#pragma unroll
        for (int i = 0; i < 2; i++) {
            int idx = tid + 256 * i;
            int r = idx >> 2, c = idx & 3;
            int grow = m0 + r;
            long long srow = grow; uint32_t by = 16;
            if (FIRST) { int tk = g_perm[grow]; if (tk < 0) { by = 0; tk = 0; } srow = tk; }
            asrc[i] = Ag + srow * (long long)KD + c * 8;
            adst[i] = swzA(r, c);
            abyt[i] = by;
        }
        const __half* bsrc[2]; uint32_t bdst[2];
#pragma unroll
        for (int i = 0; i < 2; i++) {
            int idx = tid + 256 * i;
            int k = idx >> 4, c = idx & 15;
            bsrc[i] = Bg + (long long)k * ND + n0 + c * 8;
            bdst[i] = swzB(k, c);
        }

        auto loads = [&](int kt, int st) {
            const uint32_t ao = aB + st * ASTG;
            const uint32_t bo = bB + st * BSTG;
#pragma unroll
            for (int i = 0; i < 2; i++) CP16(ao + adst[i], asrc[i] + kt * BKH, abyt[i]);
#pragma unroll
            for (int i = 0; i < 2; i++) CP16(bo + bdst[i], bsrc[i] + (long long)kt * BKH * ND, 16);
            CPCOMMIT();
        };

        float c[4][4][4];
#pragma unroll
        for (int a = 0; a < 4; a++)
#pragma unroll
            for (int b = 0; b < 4; b++)
#pragma unroll
                for (int r = 0; r < 4; r++) c[a][b][r] = 0.f;

        loads(0, 0);
        loads(1, 1);
        loads(2, 2);
        loads(3, 3);

        // 5-stage mainloop: ONE barrier per k-step, three groups of load-ahead slack.
        // iter kt: wait(loads kt done) -> barrier -> issue loads(kt+4) -> compute(kt)
        int st = 0, stn = 4;
        for (int kt = 0; kt < KT; kt++) {
            if (kt + 3 < KT)      CPWAIT3();
            else if (kt + 2 < KT) CPWAIT2();
            else if (kt + 1 < KT) CPWAIT1();
            else                  CPWAIT0();
            __syncthreads();
            if (kt + 4 < KT) loads(kt + 4, stn);

            const uint32_t ab = aB + st * ASTG;
            const uint32_t bb = bB + st * BSTG;
#pragma unroll
            for (int kk = 0; kk < 2; kk++) {
                uint32_t a[4][4], b[4][2];
#pragma unroll
                for (int mf = 0; mf < 4; mf++) {
                    int r = arb + mf * 16;
                    LDSM4(a[mf][0], a[mf][1], a[mf][2], a[mf][3],
                          ab + swzA(r, kk * 2 + acb));
                }
#pragma unroll
                for (int jp = 0; jp < 2; jp++) {
                    int k = kk * 16 + bkb;
                    uint32_t r0, r1, r2, r3;
                    LDSM4T(r0, r1, r2, r3, bb + swzB(k, bcb + jp * 2));
                    b[jp * 2][0] = r0; b[jp * 2][1] = r1;
                    b[jp * 2 + 1][0] = r2; b[jp * 2 + 1][1] = r3;
                }
#pragma unroll
                for (int mf = 0; mf < 4; mf++)
#pragma unroll
                    for (int nf = 0; nf < 4; nf++)
                        MMA16816(c[mf][nf], a[mf], b[nf]);
            }
            if (++st == NSTG) st = 0;
            if (++stn == NSTG) stn = 0;
        }

        // ---------------- epilogue ----------------
        const int lr2 = lane >> 2, lc2 = (lane & 3) * 2;
#pragma unroll
        for (int mf = 0; mf < 4; mf++) {
            const int row0 = m0 + wm * 64 + mf * 16 + lr2;
            const int row1 = row0 + 8;
            const int tk0 = g_perm[row0], tk1 = g_perm[row1];
#pragma unroll
            for (int nf = 0; nf < 4; nf++) {
                const int n = n0 + wn * 32 + nf * 8 + lc2;
                const float bz0 = bias[(long long)e * ND + n];
                const float bz1 = bias[(long long)e * ND + n + 1];
                if (FIRST) {
                    if (tk0 >= 0) {
                        float v0 = c[mf][nf][0] + bz0;
                        float v1 = c[mf][nf][1] + bz1;
                        v0 = v0 / (1.f + __expf(-v0));
                        v1 = v1 / (1.f + __expf(-v1));
                        *reinterpret_cast<__half2*>(g_h + (long long)row0 * ND + n) =
                            __floats2half2_rn(v0, v1);
                    }
                    if (tk1 >= 0) {
                        float v0 = c[mf][nf][2] + bz0;
                        float v1 = c[mf][nf][3] + bz1;
                        v0 = v0 / (1.f + __expf(-v0));
                        v1 = v1 / (1.f + __expf(-v1));
                        *reinterpret_cast<__half2*>(g_h + (long long)row1 * ND + n) =
                            __floats2half2_rn(v0, v1);
                    }
                } else {
                    if (tk0 >= 0) {
                        const float w = g_rw[row0];
                        atomicAdd(out + (long long)tk0 * ND + n,     w * (c[mf][nf][0] + bz0));
                        atomicAdd(out + (long long)tk0 * ND + n + 1, w * (c[mf][nf][1] + bz1));
                    }
                    if (tk1 >= 0) {
                        const float w = g_rw[row1];
                        atomicAdd(out + (long long)tk1 * ND + n,     w * (c[mf][nf][2] + bz0));
                        atomicAdd(out + (long long)tk1 * ND + n + 1, w * (c[mf][nf][3] + bz1));
                    }
                }
            }
        }
    }
}

// ---------------- launch ----------------
extern "C" void kernel_launch(void* const* d_in, const int* in_sizes, int n_in,
                              void* d_out, int out_size) {
    (void)in_sizes; (void)n_in; (void)out_size;
    const float* x  = (const float*)d_in[0];
    const float* wg = (const float*)d_in[1];
    const float* bg = (const float*)d_in[2];
    const float* w1 = (const float*)d_in[3];
    const float* b1 = (const float*)d_in[4];
    const float* w2 = (const float*)d_in[5];
    const float* b2 = (const float*)d_in[6];
    float* out = (float*)d_out;

    init_kernel<<<1, 32>>>();
    setup_kernel<<<2048, 256>>>(x, wg, bg, w1, out);
    offsets_kernel<<<1, 256>>>();
    scatter_kernel<<<(S_TOK + 255) / 256, 256>>>();

    moe_gemm_h<true ><<<PERSIST, 256>>>(b1, nullptr, w2);
    moe_gemm_h<false><<<PERSIST, 256>>>(b2, out, nullptr);
}

// round 17
// speedup vs baseline: 1.2679x; 1.2679x over previous
#include <cuda_runtime.h>
#include <cuda_fp16.h>
#include <cstdint>

// ---------------- problem constants ----------------
constexpr int S_TOK = 4096;
constexpr int DDIM  = 1024;
constexpr int HDIM  = 2816;
constexpr int NEXP  = 8;
constexpr int TOPK  = 2;

constexpr int BM = 128, BN = 128, BKH = 32;   // tile sizes (BKH in halves)
constexpr int MAXROWS = 9216;
constexpr int PERSIST = 304;                  // 2 CTAs/SM x 152 SMs
constexpr int CVT2 = 512;                     // w2 convert slabs (fine-grained tail packing)
constexpr int NSTG = 4;                       // cp.async pipeline stages (max at 2 CTAs/SM)

// ---------------- device scratch (allocation-free) ----------------
__device__ __align__(16) __half g_xh[(long long)S_TOK * DDIM];
__device__ __align__(16) __half g_w1h[(long long)NEXP * DDIM * HDIM];  // [E][D][H]
__device__ __align__(16) __half g_w2h[(long long)NEXP * HDIM * DDIM];  // [E][H][D]
__device__ __align__(16) __half g_h[(long long)MAXROWS * HDIM];       // silu(x@w1+b1)
__device__ int    g_perm[MAXROWS];            // row -> token (-1 = pad)
__device__ float  g_rw[MAXROWS];              // row -> gate weight
__device__ int    g_off[NEXP + 1];
__device__ int    g_cnt[NEXP];
__device__ int    g_cur[NEXP];
__device__ int    g_tick[2];                  // persistent tile tickets
__device__ int    g_tok_e[TOPK * S_TOK];
__device__ float  g_tok_w[TOPK * S_TOK];

// ---------------- PTX helpers ----------------
// .cg: bypass L1 allocation (operands are streamed once; don't pollute L1)
#define CP16(d, s, b) \
    asm volatile("cp.async.cg.shared.global [%0], [%1], 16, %2;\n" :: "r"(d), "l"(s), "r"(b))
#define CPCOMMIT() asm volatile("cp.async.commit_group;\n" ::: "memory")
#define CPWAIT2()  asm volatile("cp.async.wait_group 2;\n" ::: "memory")
#define CPWAIT1()  asm volatile("cp.async.wait_group 1;\n" ::: "memory")
#define CPWAIT0()  asm volatile("cp.async.wait_group 0;\n" ::: "memory")

#define LDSM4(r0, r1, r2, r3, a) \
    asm volatile("ldmatrix.sync.aligned.m8n8.x4.shared.b16 {%0,%1,%2,%3}, [%4];" \
                 : "=r"(r0), "=r"(r1), "=r"(r2), "=r"(r3) : "r"(a))
#define LDSM4T(r0, r1, r2, r3, a) \
    asm volatile("ldmatrix.sync.aligned.m8n8.x4.trans.shared.b16 {%0,%1,%2,%3}, [%4];" \
                 : "=r"(r0), "=r"(r1), "=r"(r2), "=r"(r3) : "r"(a))

#define MMA16816(c, a, b) \
    asm volatile("mma.sync.aligned.m16n8k16.row.col.f32.f16.f16.f32 " \
                 "{%0,%1,%2,%3},{%4,%5,%6,%7},{%8,%9},{%0,%1,%2,%3};" \
                 : "+f"((c)[0]), "+f"((c)[1]), "+f"((c)[2]), "+f"((c)[3]) \
                 : "r"((a)[0]), "r"((a)[1]), "r"((a)[2]), "r"((a)[3]), \
                   "r"((b)[0]), "r"((b)[1]))

// smem swizzles (16B chunk granularity)
__device__ __forceinline__ uint32_t swzA(int r, int c) {   // A: 128 rows x 4 chunks
    return (uint32_t)((r * 4 + (c ^ ((r >> 1) & 3))) << 4);
}
__device__ __forceinline__ uint32_t swzB(int k, int c) {   // B: 32 rows x 16 chunks
    return (uint32_t)((k * 16 + (c ^ (k & 7))) << 4);
}

// ---------------- small kernels ----------------
__global__ void init_kernel() {
    int t = threadIdx.x;
    if (t < NEXP) { g_cnt[t] = 0; g_cur[t] = 0; }
    if (t < 2) g_tick[t] = 0;
}

// Fused setup: [0,512) gate (+x->fp16), [512,1024) zero out, [1024,2048) convert w1.
__global__ void __launch_bounds__(256)
setup_kernel(const float* __restrict__ x, const float* __restrict__ wg,
             const float* __restrict__ bg, const float* __restrict__ w1,
             float* __restrict__ out) {
    __shared__ float swg[NEXP][DDIM];          // w_gate transposed, 32 KB
    const int bid = blockIdx.x, tid = threadIdx.x;
    if (bid < 512) {
        // ---- stage w_gate into smem transposed (coalesced gmem reads) ----
        for (int t = tid; t < DDIM * NEXP; t += 256) {
            float v = wg[t];
            swg[t & (NEXP - 1)][t >> 3] = v;
        }
        __syncthreads();
        // ---- gate: one warp per token ----
        int warp = bid * 8 + (tid >> 5);
        int lane = tid & 31;
        const float* xr = x + (long long)warp * DDIM;
        float xv[32];
#pragma unroll
        for (int i = 0; i < 32; i++) xv[i] = xr[lane + 32 * i];
        __half* xh = g_xh + (long long)warp * DDIM;
#pragma unroll
        for (int i = 0; i < 32; i++) xh[lane + 32 * i] = __float2half_rn(xv[i]);

        float lg[NEXP];
#pragma unroll
        for (int e = 0; e < NEXP; e++) {
            float s = 0.f;
#pragma unroll
            for (int i = 0; i < 32; i++) s += xv[i] * swg[e][lane + 32 * i];
#pragma unroll
            for (int o = 16; o > 0; o >>= 1) s += __shfl_xor_sync(0xffffffffu, s, o);
            lg[e] = s + bg[e];
        }
        if (lane == 0) {
            int e0 = 0;
#pragma unroll
            for (int e = 1; e < NEXP; e++) if (lg[e] > lg[e0]) e0 = e;
            int e1 = -1;
#pragma unroll
            for (int e = 0; e < NEXP; e++) {
                if (e == e0) continue;
                if (e1 < 0 || lg[e] > lg[e1]) e1 = e;
            }
            float z  = expf(lg[e1] - lg[e0]);
            float w0 = 1.f / (1.f + z);
            float w1v = z / (1.f + z);
            g_tok_e[warp] = e0; g_tok_e[S_TOK + warp] = e1;
            g_tok_w[warp] = w0; g_tok_w[S_TOK + warp] = w1v;
            atomicAdd(&g_cnt[e0], 1);
            atomicAdd(&g_cnt[e1], 1);
        }
    } else if (bid < 1024) {
        // ---- zero the output (poisoned by harness) ----
        float4 z; z.x = z.y = z.z = z.w = 0.f;
        float4* o4 = reinterpret_cast<float4*>(out);
        int base = (bid - 512) * 2048 + tid;
#pragma unroll
        for (int j = 0; j < 8; j++) o4[base + j * 256] = z;
    } else {
        // ---- convert w1 -> fp16 ----
        int slab = bid - 1024;                      // 1024 slabs * 5632 chunks
        const float4* s4 = reinterpret_cast<const float4*>(w1);
        long long base = (long long)slab * 5632 + tid;
#pragma unroll
        for (int j = 0; j < 22; j++) {
            long long i = base + j * 256;
            float4 v = s4[i];
            __half2* d = reinterpret_cast<__half2*>(g_w1h) + i * 2;
            d[0] = __floats2half2_rn(v.x, v.y);
            d[1] = __floats2half2_rn(v.z, v.w);
        }
    }
}

__global__ void offsets_kernel() {
    if (threadIdx.x == 0) {
        int o = 0;
        for (int e = 0; e < NEXP; e++) {
            g_off[e] = o;
            o += ((g_cnt[e] + BM - 1) / BM) * BM;
        }
        g_off[NEXP] = o;
    }
    for (int i = threadIdx.x; i < MAXROWS; i += blockDim.x) g_perm[i] = -1;
}

// warp-aggregated scatter: one atomic per (warp, expert-group) instead of per thread
__global__ void scatter_kernel() {
    int t = blockIdx.x * blockDim.x + threadIdx.x;
    int lane = threadIdx.x & 31;
    if (t >= S_TOK) return;
#pragma unroll
    for (int k = 0; k < TOPK; k++) {
        int e = g_tok_e[k * S_TOK + t];
        unsigned grp = __match_any_sync(0xffffffffu, e);
        int leader = __ffs(grp) - 1;
        int rank = __popc(grp & ((1u << lane) - 1u));
        int base = 0;
        if (lane == leader) base = atomicAdd(&g_cur[e], __popc(grp));
        base = __shfl_sync(0xffffffffu, base, leader);
        int p = g_off[e] + base + rank;
        g_perm[p] = t;
        g_rw[p]   = g_tok_w[k * S_TOK + t];
    }
}

// w2 fp32->fp16 convert, one slab (runs as cheap tail tickets of GEMM1)
__device__ __forceinline__ void cvt_w2_slab(const float* __restrict__ w2,
                                            int slab, int tid) {
    const float4* s4 = reinterpret_cast<const float4*>(w2);
    long long base = (long long)slab * 11264 + tid;   // 512 slabs * 11264 chunks
#pragma unroll 4
    for (int j = 0; j < 44; j++) {
        long long i = base + (long long)j * 256;
        float4 v = s4[i];
        __half2* d = reinterpret_cast<__half2*>(g_w2h) + i * 2;
        d[0] = __floats2half2_rn(v.x, v.y);
        d[1] = __floats2half2_rn(v.z, v.w);
    }
}

// ---------------- persistent fp16 grouped GEMM (4-stage pipeline) ----------------
// FIRST : g_h = silu(gather(g_xh) @ g_w1h[e] + b1[e])     (K=1024, N=2816)
//         + w2 fp16 conversion tickets appended at the END of the stream
// !FIRST: out[token] += g_rw[row] * (g_h[row] @ g_w2h[e] + b2[e])  (K=2816, N=1024)
template <bool FIRST>
__global__ void __launch_bounds__(256, 2)
moe_gemm_h(const float* __restrict__ bias, float* __restrict__ out,
           const float* __restrict__ w2raw) {
    constexpr int KD = FIRST ? DDIM : HDIM;
    constexpr int ND = FIRST ? HDIM : DDIM;
    constexpr int KT = KD / BKH;
    constexpr int NT = ND / BN;
    constexpr uint32_t ASTG = BM * BKH * 2;   // 8 KB
    constexpr uint32_t BSTG = BKH * BN * 2;   // 8 KB

    __shared__ __align__(16) __half sA[NSTG][BM * BKH];   // 32 KB
    __shared__ __align__(16) __half sB[NSTG][BKH * BN];   // 32 KB
    __shared__ int s_tile;

    const int tid = threadIdx.x, lane = tid & 31, wid = tid >> 5;
    const uint32_t aB = (uint32_t)__cvta_generic_to_shared(&sA[0][0]);
    const uint32_t bB = (uint32_t)__cvta_generic_to_shared(&sB[0][0]);

    const int MT = g_off[NEXP] >> 7;     // active M tiles
    const int ntiles = MT * NT;
    const int total = ntiles + (FIRST ? CVT2 : 0);

    // warp layout: 2 (m) x 4 (n); warp tile 64 x 32
    const int wm = wid & 1, wn = wid >> 1;
    const int tl = lane >> 3, lr = lane & 7;
    const int arb = wm * 64 + (tl & 1) * 8 + lr;   // A ldmatrix row base
    const int acb = tl >> 1;                       // A chunk add (k8 block)
    const int bkb = (tl & 1) * 8 + lr;             // B k base within k16
    const int bcb = wn * 4 + (tl >> 1);            // B chunk base

    for (;;) {
        __syncthreads();
        if (tid == 0) s_tile = atomicAdd(&g_tick[FIRST ? 0 : 1], 1);
        __syncthreads();
        const int t = s_tile;
        if (t >= total) break;

        if (FIRST && t >= ntiles) {          // cheap cvt tickets pack the last wave
            cvt_w2_slab(w2raw, t - ntiles, tid);
            continue;
        }
        const int m0 = (t % MT) * BM;        // m-fastest: concurrent CTAs share B tiles
        const int n0 = (t / MT) * BN;

        int e = 0;
#pragma unroll
        for (int i = 1; i < NEXP; i++) if (m0 >= g_off[i]) e = i;

        const __half* Ag = FIRST ? g_xh : g_h;
        const __half* Bg = (FIRST ? g_w1h : g_w2h) + (long long)e * KD * ND;

        // ---- per-thread cp.async plans (2 x 16B chunks each for A and B) ----
        const __half* asrc[2]; uint32_t adst[2], abyt[2];
#pragma unroll
        for (int i = 0; i < 2; i++) {
            int idx = tid + 256 * i;
            int r = idx >> 2, c = idx & 3;
            int grow = m0 + r;
            long long srow = grow; uint32_t by = 16;
            if (FIRST) { int tk = g_perm[grow]; if (tk < 0) { by = 0; tk = 0; } srow = tk; }
            asrc[i] = Ag + srow * (long long)KD + c * 8;
            adst[i] = swzA(r, c);
            abyt[i] = by;
        }
        const __half* bsrc[2]; uint32_t bdst[2];
#pragma unroll
        for (int i = 0; i < 2; i++) {
            int idx = tid + 256 * i;
            int k = idx >> 4, c = idx & 15;
            bsrc[i] = Bg + (long long)k * ND + n0 + c * 8;
            bdst[i] = swzB(k, c);
        }

        auto loads = [&](int kt, int st) {
            const uint32_t ao = aB + st * ASTG;
            const uint32_t bo = bB + st * BSTG;
#pragma unroll
            for (int i = 0; i < 2; i++) CP16(ao + adst[i], asrc[i] + kt * BKH, abyt[i]);
#pragma unroll
            for (int i = 0; i < 2; i++) CP16(bo + bdst[i], bsrc[i] + (long long)kt * BKH * ND, 16);
            CPCOMMIT();
        };

        float c[4][4][4];
#pragma unroll
        for (int a = 0; a < 4; a++)
#pragma unroll
            for (int b = 0; b < 4; b++)
#pragma unroll
                for (int r = 0; r < 4; r++) c[a][b][r] = 0.f;

        loads(0, 0);
        loads(1, 1);
        loads(2, 2);

        // 4-stage mainloop: ONE barrier per k-step, two groups of load-ahead slack.
        // iter kt: wait(loads kt done) -> barrier -> issue loads(kt+3) -> compute(kt)
        int st = 0, stn = 3;
        for (int kt = 0; kt < KT; kt++) {
            if (kt + 2 < KT)      CPWAIT2();
            else if (kt + 1 < KT) CPWAIT1();
            else                  CPWAIT0();
            __syncthreads();
            if (kt + 3 < KT) loads(kt + 3, stn);

            const uint32_t ab = aB + st * ASTG;
            const uint32_t bb = bB + st * BSTG;
#pragma unroll
            for (int kk = 0; kk < 2; kk++) {
                uint32_t a[4][4], b[4][2];
#pragma unroll
                for (int mf = 0; mf < 4; mf++) {
                    int r = arb + mf * 16;
                    LDSM4(a[mf][0], a[mf][1], a[mf][2], a[mf][3],
                          ab + swzA(r, kk * 2 + acb));
                }
#pragma unroll
                for (int jp = 0; jp < 2; jp++) {
                    int k = kk * 16 + bkb;
                    uint32_t r0, r1, r2, r3;
                    LDSM4T(r0, r1, r2, r3, bb + swzB(k, bcb + jp * 2));
                    b[jp * 2][0] = r0; b[jp * 2][1] = r1;
                    b[jp * 2 + 1][0] = r2; b[jp * 2 + 1][1] = r3;
                }
#pragma unroll
                for (int mf = 0; mf < 4; mf++)
#pragma unroll
                    for (int nf = 0; nf < 4; nf++)
                        MMA16816(c[mf][nf], a[mf], b[nf]);
            }
            if (++st == NSTG) st = 0;
            if (++stn == NSTG) stn = 0;
        }

        // ---------------- epilogue ----------------
        const int lr2 = lane >> 2, lc2 = (lane & 3) * 2;
#pragma unroll
        for (int mf = 0; mf < 4; mf++) {
            const int row0 = m0 + wm * 64 + mf * 16 + lr2;
            const int row1 = row0 + 8;
            const int tk0 = g_perm[row0], tk1 = g_perm[row1];
#pragma unroll
            for (int nf = 0; nf < 4; nf++) {
                const int n = n0 + wn * 32 + nf * 8 + lc2;
                const float bz0 = bias[(long long)e * ND + n];
                const float bz1 = bias[(long long)e * ND + n + 1];
                if (FIRST) {
                    if (tk0 >= 0) {
                        float v0 = c[mf][nf][0] + bz0;
                        float v1 = c[mf][nf][1] + bz1;
                        v0 = v0 / (1.f + __expf(-v0));
                        v1 = v1 / (1.f + __expf(-v1));
                        *reinterpret_cast<__half2*>(g_h + (long long)row0 * ND + n) =
                            __floats2half2_rn(v0, v1);
                    }
                    if (tk1 >= 0) {
                        float v0 = c[mf][nf][2] + bz0;
                        float v1 = c[mf][nf][3] + bz1;
                        v0 = v0 / (1.f + __expf(-v0));
                        v1 = v1 / (1.f + __expf(-v1));
                        *reinterpret_cast<__half2*>(g_h + (long long)row1 * ND + n) =
                            __floats2half2_rn(v0, v1);
                    }
                } else {
                    if (tk0 >= 0) {
                        const float w = g_rw[row0];
                        atomicAdd(out + (long long)tk0 * ND + n,     w * (c[mf][nf][0] + bz0));
                        atomicAdd(out + (long long)tk0 * ND + n + 1, w * (c[mf][nf][1] + bz1));
                    }
                    if (tk1 >= 0) {
                        const float w = g_rw[row1];
                        atomicAdd(out + (long long)tk1 * ND + n,     w * (c[mf][nf][2] + bz0));
                        atomicAdd(out + (long long)tk1 * ND + n + 1, w * (c[mf][nf][3] + bz1));
                    }
                }
            }
        }
    }
}

// ---------------- launch ----------------
extern "C" void kernel_launch(void* const* d_in, const int* in_sizes, int n_in,
                              void* d_out, int out_size) {
    (void)in_sizes; (void)n_in; (void)out_size;
    const float* x  = (const float*)d_in[0];
    const float* wg = (const float*)d_in[1];
    const float* bg = (const float*)d_in[2];
    const float* w1 = (const float*)d_in[3];
    const float* b1 = (const float*)d_in[4];
    const float* w2 = (const float*)d_in[5];
    const float* b2 = (const float*)d_in[6];
    float* out = (float*)d_out;

    init_kernel<<<1, 32>>>();
    setup_kernel<<<2048, 256>>>(x, wg, bg, w1, out);
    offsets_kernel<<<1, 256>>>();
    scatter_kernel<<<(S_TOK + 255) / 256, 256>>>();

    moe_gemm_h<true ><<<PERSIST, 256>>>(b1, nullptr, w2);
    moe_gemm_h<false><<<PERSIST, 256>>>(b2, out, nullptr);
}